// round 11
// baseline (speedup 1.0000x reference)
#include <cuda_runtime.h>
#include <cuda_bf16.h>
#include <cstdint>

#define BB   16
#define NN   2048
#define FINN 64
#define FOUT 32
#define KK   16
#define MT   128
#define TPB  512
#define CH   512             /* j rows per chunk */
#define NCHK 4
#define STR  56              /* padded bf16 per augmented row (48 used) */
#define STRB 112             /* bytes per padded row */
#define EPSF 1e-8f
#define NM   2.9150f         /* -log(-log(eps)) = 2.91347 */
#define ERRD 1.0f            /* one-sided bf16-MMA D error budget (true worst ~0.65) */
#define CAP  160
#define H_ELEMS (BB*NN*FOUT)
#define BNK     (BB*NN*KK)

__device__ float g_sq[BB*NN];
__device__ __nv_bfloat16 g_A[(size_t)BB*NN*STR];
__device__ __nv_bfloat16 g_B[(size_t)BB*NN*STR];

typedef unsigned long long ull;

static __device__ __forceinline__ uint32_t smem_u32(const void* p){
    uint32_t a;
    asm("{ .reg .u64 t; cvta.to.shared.u64 t, %1; cvt.u32.u64 %0, t; }" : "=r"(a) : "l"(p));
    return a;
}
static __device__ __forceinline__ ull ffma2(ull a, ull b, ull c){
    ull d; asm("fma.rn.f32x2 %0, %1, %2, %3;" : "=l"(d) : "l"(a), "l"(b), "l"(c));
    return d;
}
static __device__ __forceinline__ float2 unpackf2(ull v){
    float2 f; uint32_t lo, hi;
    asm("mov.b64 {%0, %1}, %2;" : "=r"(lo), "=r"(hi) : "l"(v));
    f.x = __uint_as_float(lo); f.y = __uint_as_float(hi);
    return f;
}
static __device__ __forceinline__ float finf(){ return __int_as_float(0x7f800000); }
static __device__ __forceinline__ bool lessvi(float v1, int j1, float v2, int j2){
    return (v1 < v2) || (v1 == v2 && j1 < j2);
}
static __device__ __forceinline__ void bsort32(int lane, float& v, int& j){
    #pragma unroll
    for (int k = 2; k <= 32; k <<= 1){
        #pragma unroll
        for (int s = k >> 1; s > 0; s >>= 1){
            float ov = __shfl_xor_sync(0xffffffffu, v, s);
            int   oj = __shfl_xor_sync(0xffffffffu, j, s);
            bool takeMin = (((lane & k) == 0) == ((lane & s) == 0));
            bool oless   = lessvi(ov, oj, v, j);
            if (takeMin ? oless : !oless){ v = ov; j = oj; }
        }
    }
}

// ---------------- kernel 1: h = x@W, sq, augmented bf16 rows ----------------
__global__ void k_embed(const float* __restrict__ x, const float* __restrict__ W,
                        float* __restrict__ hout){
    __shared__ float Ws[FINN*FOUT];
    __shared__ float xs[8][FINN];
    int t = threadIdx.x;
    for (int i = t; i < FINN*FOUT; i += 256) Ws[i] = W[i];
    int row0 = blockIdx.x * 8;
    for (int i = t; i < 8*FINN; i += 256){
        int r = i / FINN, f = i % FINN;
        xs[r][f] = x[(size_t)(row0 + r)*FINN + f];
    }
    __syncthreads();
    int r = t >> 5, d = t & 31;
    float acc = 0.f;
    #pragma unroll
    for (int f = 0; f < FINN; ++f)
        acc = fmaf(xs[r][f], Ws[f*FOUT + d], acc);
    int row = row0 + r;
    hout[(size_t)row*FOUT + d] = acc;
    __nv_bfloat16 hbf = __float2bfloat16(acc);
    g_A[(size_t)row*STR + d] = hbf;
    g_B[(size_t)row*STR + d] = __float2bfloat16(-2.f*__bfloat162float(hbf));
    float v = acc * acc;
    #pragma unroll
    for (int o = 16; o; o >>= 1) v += __shfl_xor_sync(0xffffffffu, v, o);
    if (d == 0) g_sq[row] = v;
    // aug cols 32..55: A=[sq,1,4,0..], B=[1,sq,4,0..] -> D~ = -2h.h + sqi + sqj + 16
    if (d < 24){
        float av = 0.f, bv = 0.f;
        if (d == 0){ av = v;   bv = 1.f; }
        else if (d == 1){ av = 1.f; bv = v; }
        else if (d == 2){ av = 4.f; bv = 4.f; }
        g_A[(size_t)row*STR + 32 + d] = __float2bfloat16(av);
        g_B[(size_t)row*STR + 32 + d] = __float2bfloat16(bv);
    }
}

// smem layout (bytes)
#define O_BUF  0u                 /* 2 x CH*STRB = 114688 */
#define O_HI   114688u            /* 128*32 f32 = 16384 */
#define O_CAND 131072u            /* 128*CAP int = 81920 */
#define O_PK   212992u            /* 128*16 keys = 8192 */
#define O_TAU  221184u            /* 128 f32 */
#define O_SQI  221696u            /* 128 f32 */
#define O_CNT  222208u            /* 128 int */
#define SMEM_DYN 222720u

// ---------------- kernel 2: HMMA gram + pruned exact gumbel top-k ----------------
__global__ __launch_bounds__(TPB, 1)
void k_main(const float* __restrict__ h, const float* __restrict__ q,
            const float* __restrict__ temp,
            float* __restrict__ e0, float* __restrict__ lp){
    extern __shared__ char sm[];
    char*  bufB  = sm + O_BUF;
    float* hiF   = (float*)(sm + O_HI);
    int*   candJ = (int*)(sm + O_CAND);
    uint32_t* probeK = (uint32_t*)(sm + O_PK);
    float* tauS  = (float*)(sm + O_TAU);
    float* sqiS  = (float*)(sm + O_SQI);
    int*   candC = (int*)(sm + O_CNT);

    const int t = threadIdx.x, w = t >> 5, lane = t & 31;
    const int b  = blockIdx.x >> 4;
    const int i0 = (blockIdx.x & 15) * MT;
    const float* hb = h + (size_t)b*NN*FOUT;
    const char* gBp = (const char*)(g_B + (size_t)b*NN*STR);
    const float ET = expf(fminf(fmaxf(temp[0], -5.f), 5.f));

    for (int g = t; g < MT*FOUT/4; g += TPB)
        ((float4*)hiF)[g] = ((const float4*)(hb + (size_t)i0*FOUT))[g];
    if (t < MT){ sqiS[t] = g_sq[b*NN + i0 + t]; candC[t] = 0; }

    // A fragments (3 k-steps of m16n8k16), loaded once from global
    const int g8 = w & 7;
    const int jsub = (w >> 3) * 256;
    uint32_t afr[3][4];
    {
        const char* pr0 = (const char*)(g_A + (size_t)(b*NN + i0 + g8*16 + (lane>>2))*STR);
        const char* pr1 = pr0 + 8*STRB;
        #pragma unroll
        for (int ks = 0; ks < 3; ++ks){
            int byt = (ks*16 + 2*(lane&3))*2;
            afr[ks][0] = *(const uint32_t*)(pr0 + byt);
            afr[ks][1] = *(const uint32_t*)(pr1 + byt);
            afr[ks][2] = *(const uint32_t*)(pr0 + byt + 16);
            afr[ks][3] = *(const uint32_t*)(pr1 + byt + 16);
        }
    }

    const uint32_t uBuf = smem_u32(bufB);
    uint32_t accK[4];
    float tau0 = 0.f, tau1 = 0.f;

    for (int pass = 0; pass < 2; ++pass){
        if (pass == 0){ accK[0]=accK[1]=accK[2]=accK[3]=0xffffffffu; }
        else {
            tau0 = tauS[g8*16 + (lane>>2)];
            tau1 = tauS[g8*16 + (lane>>2) + 8];
        }
        uint4 st[7];
        #pragma unroll
        for (int i2 = 0; i2 < 7; ++i2)
            st[i2] = *(const uint4*)(gBp + (size_t)(i2*TPB + t)*16);

        for (int c = 0; c < NCHK; ++c){
            __syncthreads();
            {   // flat copy: chunk is contiguous 57344 bytes
                char* dst = bufB + (c&1)*(CH*STRB);
                #pragma unroll
                for (int i2 = 0; i2 < 7; ++i2)
                    *(uint4*)(dst + (size_t)(i2*TPB + t)*16) = st[i2];
            }
            __syncthreads();
            if (c + 1 < NCHK){
                const char* src = gBp + (size_t)(c+1)*CH*STRB;
                #pragma unroll
                for (int i2 = 0; i2 < 7; ++i2)
                    st[i2] = *(const uint4*)(src + (size_t)(i2*TPB + t)*16);
            }
            const uint32_t bbase = uBuf + (uint32_t)(c&1)*(CH*STRB);
            const int jc = c*CH + jsub;
            #pragma unroll 4
            for (int tile = 0; tile < 32; ++tile){
                uint32_t baddr = bbase + (uint32_t)(jsub + tile*8 + (lane>>2))*STRB + (lane&3)*4;
                float d0=0.f, d1=0.f, d2=0.f, d3=0.f;
                #pragma unroll
                for (int ks = 0; ks < 3; ++ks){
                    uint32_t b0, b1;
                    asm volatile("ld.shared.b32 %0,[%1];" : "=r"(b0) : "r"(baddr + ks*32));
                    asm volatile("ld.shared.b32 %0,[%1];" : "=r"(b1) : "r"(baddr + ks*32 + 16));
                    asm volatile("mma.sync.aligned.m16n8k16.row.col.f32.bf16.bf16.f32 "
                        "{%0,%1,%2,%3}, {%4,%5,%6,%7}, {%8,%9}, {%0,%1,%2,%3};"
                        : "+f"(d0), "+f"(d1), "+f"(d2), "+f"(d3)
                        : "r"(afr[ks][0]), "r"(afr[ks][1]), "r"(afr[ks][2]), "r"(afr[ks][3]),
                          "r"(b0), "r"(b1));
                }
                const int n0 = jc + tile*8 + 2*(lane&3);
                if (pass == 0){
                    accK[0] = min(accK[0], (__float_as_uint(d0) & ~2047u) | (uint32_t)n0);
                    accK[1] = min(accK[1], (__float_as_uint(d1) & ~2047u) | (uint32_t)(n0+1));
                    accK[2] = min(accK[2], (__float_as_uint(d2) & ~2047u) | (uint32_t)n0);
                    accK[3] = min(accK[3], (__float_as_uint(d3) & ~2047u) | (uint32_t)(n0+1));
                } else {
                    bool h0 = d0 <= tau0, h1 = d1 <= tau0, h2 = d2 <= tau1, h3 = d3 <= tau1;
                    if (__ballot_sync(0xffffffffu, h0|h1|h2|h3)){
                        int row0 = g8*16 + (lane>>2), row1 = row0 + 8;
                        if (h0){ int ix = atomicAdd(&candC[row0],1); if (ix<CAP) candJ[row0*CAP+ix] = n0; }
                        if (h1){ int ix = atomicAdd(&candC[row0],1); if (ix<CAP) candJ[row0*CAP+ix] = n0+1; }
                        if (h2){ int ix = atomicAdd(&candC[row1],1); if (ix<CAP) candJ[row1*CAP+ix] = n0; }
                        if (h3){ int ix = atomicAdd(&candC[row1],1); if (ix<CAP) candJ[row1*CAP+ix] = n0+1; }
                    }
                }
            }
        }
        if (pass == 0){
            // publish 16 probes per row, compute per-row threshold
            int rr0 = g8*16 + (lane>>2);
            int bse = rr0*16 + (w>>3)*8 + (lane&3)*2;
            probeK[bse] = accK[0]; probeK[bse+1] = accK[1];
            int bse1 = (rr0+8)*16 + (w>>3)*8 + (lane&3)*2;
            probeK[bse1] = accK[2]; probeK[bse1+1] = accK[3];
            __syncthreads();
            {
                const int row = t >> 2, p = t & 3;
                const float* qrow = q + ((size_t)b*NN + (i0 + row))*NN;
                float T = -finf();
                #pragma unroll
                for (int e = 0; e < 4; ++e){
                    uint32_t key = probeK[row*16 + p*4 + e];
                    int j = (int)(key & 2047u);
                    float Dq = __uint_as_float(key & ~2047u) - 16.f;
                    float s = ET * fmaxf(Dq, 0.f);
                    float lq = s - logf(-logf(__ldg(qrow + j) + EPSF));
                    T = fmaxf(T, lq);
                }
                T = fmaxf(T, __shfl_xor_sync(0xffffffffu, T, 1));
                T = fmaxf(T, __shfl_xor_sync(0xffffffffu, T, 2));
                if (p == 0) tauS[row] = (T + NM)/ET + 2.f*ERRD + 0.2f + 16.f;
            }
            __syncthreads();
        }
    }
    __syncthreads();

    // ---- final exact merge: warp w handles rows w*8 .. w*8+7 ----
    for (int rr = 0; rr < 8; ++rr){
        const int row = w*8 + rr, n = i0 + row;
        const float* qrow = q + ((size_t)b*NN + n)*NN;
        const ull* wi = (const ull*)(hiF + row*FOUT);
        const float sqv = sqiS[row];
        float bv = finf(); int bj = 0x7fffffff;
        const int ccount = candC[row];

        if (ccount <= CAP){
            // normal path: exact merge over compacted candidates
            for (int s0 = 0; s0 < ccount; s0 += 16){
                float v = bv; int jj = bj;
                if (lane >= 16){
                    int idx = s0 + lane - 16;
                    if (idx < ccount){
                        int j = candJ[row*CAP + idx];
                        const ull* aj = (const ull*)(hb + (size_t)j*FOUT);
                        ull acc = 0ull;
                        #pragma unroll
                        for (int dp = 0; dp < 16; ++dp) acc = ffma2(aj[dp], wi[dp], acc);
                        float2 f = unpackf2(acc);
                        float s = ET * fmaxf(sqv + g_sq[b*NN + j] - 2.f*(f.x + f.y), 0.f);
                        v = s - logf(-logf(__ldg(qrow + j) + EPSF)); jj = j;
                    } else { v = finf(); jj = 0x7fffffff; }
                }
                bsort32(lane, v, jj);
                bv = v; bj = jj;
            }
        } else {
            // overflow fallback (rare): exact fp32 rescan of all j for this row
            int* stg = candJ + row*CAP;
            const float tauD = tauS[row] - 16.f - ERRD;  // exact-D threshold (provably safe)
            int cnt = 0;
            const unsigned lm = (1u << lane) - 1u;
            for (int m = 0; m < NN/32; ++m){
                int j = lane + 32*m;
                const ull* aj = (const ull*)(hb + (size_t)j*FOUT);
                ull acc = 0ull;
                #pragma unroll
                for (int dp = 0; dp < 16; ++dp) acc = ffma2(aj[dp], wi[dp], acc);
                float2 f = unpackf2(acc);
                float Dx = sqv + g_sq[b*NN + j] - 2.f*(f.x + f.y);
                bool cb = (Dx <= tauD);
                unsigned mk = __ballot_sync(0xffffffffu, cb);
                if (mk){
                    int pos = __popc(mk & lm);
                    if (cb) stg[cnt + pos] = j;
                    cnt += __popc(mk);
                    __syncwarp();
                    while (cnt >= 16){
                        float v = bv; int jj = bj;
                        if (lane >= 16){
                            int j2 = stg[cnt - 16 + (lane - 16)];
                            const ull* a2 = (const ull*)(hb + (size_t)j2*FOUT);
                            ull ac2 = 0ull;
                            #pragma unroll
                            for (int dp = 0; dp < 16; ++dp) ac2 = ffma2(a2[dp], wi[dp], ac2);
                            float2 f2 = unpackf2(ac2);
                            float s = ET * fmaxf(sqv + g_sq[b*NN + j2] - 2.f*(f2.x + f2.y), 0.f);
                            v = s - logf(-logf(__ldg(qrow + j2) + EPSF)); jj = j2;
                        }
                        bsort32(lane, v, jj);
                        bv = v; bj = jj;
                        cnt -= 16;
                    }
                }
            }
            if (cnt > 0){
                float v = bv; int jj = bj;
                if (lane >= 16){
                    int idx = lane - 16;
                    if (idx < cnt){
                        int j2 = stg[idx];
                        const ull* a2 = (const ull*)(hb + (size_t)j2*FOUT);
                        ull ac2 = 0ull;
                        #pragma unroll
                        for (int dp = 0; dp < 16; ++dp) ac2 = ffma2(a2[dp], wi[dp], ac2);
                        float2 f2 = unpackf2(ac2);
                        float s = ET * fmaxf(sqv + g_sq[b*NN + j2] - 2.f*(f2.x + f2.y), 0.f);
                        v = s - logf(-logf(__ldg(qrow + j2) + EPSF)); jj = j2;
                    } else { v = finf(); jj = 0x7fffffff; }
                }
                bsort32(lane, v, jj);
                bv = v; bj = jj;
            }
        }

        if (lane < KK){
            size_t base = ((size_t)b*NN + n)*KK + lane;
            lp[base] = -bv;
            e0[base] = (float)(bj + b*NN);
            e0[base + BNK] = (float)(n + b*NN);
        }
        __syncwarp();
    }
}

extern "C" void kernel_launch(void* const* d_in, const int* in_sizes, int n_in,
                              void* d_out, int out_size){
    const float* x    = (const float*)d_in[0];
    const float* W    = (const float*)d_in[1];
    const float* temp = (const float*)d_in[2];
    const float* q    = (const float*)d_in[3];
    float* out  = (float*)d_out;
    float* hout = out;                   // [B,N,Fout]
    float* e0   = out + H_ELEMS;         // [2, B*N*K]
    float* lp   = out + H_ELEMS + 2*BNK; // [B,N,K]

    k_embed<<<BB*NN/8, 256>>>(x, W, hout);

    cudaFuncSetAttribute(k_main, cudaFuncAttributeMaxDynamicSharedMemorySize, SMEM_DYN);
    k_main<<<BB*(NN/MT), TPB, SMEM_DYN>>>(hout, q, temp, e0, lp);
}

// round 12
// speedup vs baseline: 1.2795x; 1.2795x over previous
#include <cuda_runtime.h>
#include <cuda_bf16.h>
#include <cstdint>

#define BB   16
#define NN   2048
#define FINN 64
#define FOUT 32
#define KK   16
#define MT   16              /* i-rows per block */
#define TPB  512
#define STR  56              /* bf16 per augmented row */
#define STRB 112             /* bytes per augmented row */
#define SSTR 1036            /* padded words per score-cache row */
#define EPSF 1e-8f
#define NM   2.9150f         /* -log(-log(eps)) = 2.91347 */
#define ERRD 1.0f
#define H_ELEMS (BB*NN*FOUT)
#define BNK     (BB*NN*KK)

__device__ float g_sq[BB*NN];
__device__ __nv_bfloat16 g_A[(size_t)BB*NN*STR];
__device__ __nv_bfloat16 g_B[(size_t)BB*NN*STR];

typedef unsigned long long ull;

static __device__ __forceinline__ ull ffma2(ull a, ull b, ull c){
    ull d; asm("fma.rn.f32x2 %0, %1, %2, %3;" : "=l"(d) : "l"(a), "l"(b), "l"(c));
    return d;
}
static __device__ __forceinline__ float2 unpackf2(ull v){
    float2 f; uint32_t lo, hi;
    asm("mov.b64 {%0, %1}, %2;" : "=r"(lo), "=r"(hi) : "l"(v));
    f.x = __uint_as_float(lo); f.y = __uint_as_float(hi);
    return f;
}
static __device__ __forceinline__ float finf(){ return __int_as_float(0x7f800000); }
static __device__ __forceinline__ bool lessvi(float v1, int j1, float v2, int j2){
    return (v1 < v2) || (v1 == v2 && j1 < j2);
}
static __device__ __forceinline__ void bsort32(int lane, float& v, int& j){
    #pragma unroll
    for (int k = 2; k <= 32; k <<= 1){
        #pragma unroll
        for (int s = k >> 1; s > 0; s >>= 1){
            float ov = __shfl_xor_sync(0xffffffffu, v, s);
            int   oj = __shfl_xor_sync(0xffffffffu, j, s);
            bool takeMin = (((lane & k) == 0) == ((lane & s) == 0));
            bool oless   = lessvi(ov, oj, v, j);
            if (takeMin ? oless : !oless){ v = ov; j = oj; }
        }
    }
}

// ---------------- kernel 1: h = x@W, sq, augmented bf16 rows ----------------
__global__ void k_embed(const float* __restrict__ x, const float* __restrict__ W,
                        float* __restrict__ hout){
    __shared__ float Ws[FINN*FOUT];
    __shared__ float xs[8][FINN];
    int t = threadIdx.x;
    for (int i = t; i < FINN*FOUT; i += 256) Ws[i] = W[i];
    int row0 = blockIdx.x * 8;
    for (int i = t; i < 8*FINN; i += 256){
        int r = i / FINN, f = i % FINN;
        xs[r][f] = x[(size_t)(row0 + r)*FINN + f];
    }
    __syncthreads();
    int r = t >> 5, d = t & 31;
    float acc = 0.f;
    #pragma unroll
    for (int f = 0; f < FINN; ++f)
        acc = fmaf(xs[r][f], Ws[f*FOUT + d], acc);
    int row = row0 + r;
    hout[(size_t)row*FOUT + d] = acc;
    __nv_bfloat16 hbf = __float2bfloat16(acc);
    g_A[(size_t)row*STR + d] = hbf;
    g_B[(size_t)row*STR + d] = __float2bfloat16(-2.f*__bfloat162float(hbf));
    float v = acc * acc;
    #pragma unroll
    for (int o = 16; o; o >>= 1) v += __shfl_xor_sync(0xffffffffu, v, o);
    if (d == 0) g_sq[row] = v;
    // aug cols 32..55: A=[sq,1,4,0..], B=[1,sq,4,0..] -> D~ = -2h.h + sqi + sqj + 16
    if (d < 24){
        float av = 0.f, bv = 0.f;
        if (d == 0){ av = v;   bv = 1.f; }
        else if (d == 1){ av = 1.f; bv = v; }
        else if (d == 2){ av = 4.f; bv = 4.f; }
        g_A[(size_t)row*STR + 32 + d] = __float2bfloat16(av);
        g_B[(size_t)row*STR + 32 + d] = __float2bfloat16(bv);
    }
}

// dyn smem layout (bytes)
#define O_BUF  0u                 /* 1024 rows * 112B B-stage        = 114688 */
#define O_SS   114688u            /* 16 * SSTR * 4 bf16x2 cache      = 66304  */
#define O_HI   180992u            /* 16*32 f32 exact h rows          = 2048   */
#define O_PK   183040u            /* 16*68 keys (padded)             = 4352   */
#define O_STG  187392u            /* 16*48 candidate stage           = 3072   */
#define O_SQI  190464u            /* 16 f32                          = 64     */
#define SMEM_DYN 190528u

// ---------------- kernel 2: HMMA gram + epilogue-min + exact gumbel top-k ----------------
__global__ __launch_bounds__(TPB, 1)
void k_main(const float* __restrict__ h, const float* __restrict__ q,
            const float* __restrict__ temp,
            float* __restrict__ e0, float* __restrict__ lp){
    extern __shared__ char sm[];
    char*     bufB  = sm + O_BUF;
    uint32_t* sS    = (uint32_t*)(sm + O_SS);
    float*    hiF   = (float*)(sm + O_HI);
    uint32_t* probeK= (uint32_t*)(sm + O_PK);
    int*      stgAll= (int*)(sm + O_STG);
    float*    sqiS  = (float*)(sm + O_SQI);

    const int t = threadIdx.x, w = t >> 5, lane = t & 31;
    const int b  = blockIdx.x >> 7;          /* 128 i-tiles per batch */
    const int i0 = (blockIdx.x & 127) * MT;
    const float* hb = h + (size_t)b*NN*FOUT;
    const char* gBp = (const char*)(g_B + (size_t)b*NN*STR);
    const float ET = expf(fminf(fmaxf(temp[0], -5.f), 5.f));

    for (int g = t; g < MT*FOUT/4; g += TPB)
        ((float4*)hiF)[g] = ((const float4*)(hb + (size_t)i0*FOUT))[g];
    if (t < MT) sqiS[t] = g_sq[b*NN + i0 + t];

    // A fragments: 3 k-steps of m16n8k16, rows i0 + (lane>>2), +8 (validated mapping)
    uint32_t afr[3][4];
    {
        const char* pr0 = (const char*)(g_A + (size_t)(b*NN + i0 + (lane>>2))*STR);
        const char* pr1 = pr0 + 8*STRB;
        #pragma unroll
        for (int ks = 0; ks < 3; ++ks){
            int byt = ks*32 + (lane&3)*4;
            afr[ks][0] = *(const uint32_t*)(pr0 + byt);
            afr[ks][1] = *(const uint32_t*)(pr1 + byt);
            afr[ks][2] = *(const uint32_t*)(pr0 + byt + 16);
            afr[ks][3] = *(const uint32_t*)(pr1 + byt + 16);
        }
    }

    uint32_t kmin0 = 0xffffffffu, kmin1 = 0xffffffffu;
    const int r0 = lane >> 2, r1 = (lane >> 2) + 8;

    // ---- gram: 2 stages of 1024 j-rows; HMMA + pack + key-min epilogue ----
    for (int s = 0; s < 2; ++s){
        {   // coalesced copy of stage: 1024 rows * 112B
            uint4 r[14];
            const char* src = gBp + (size_t)s*114688u;
            #pragma unroll
            for (int i2 = 0; i2 < 14; ++i2)
                r[i2] = *(const uint4*)(src + (size_t)(i2*TPB + t)*16);
            #pragma unroll
            for (int i2 = 0; i2 < 14; ++i2)
                *(uint4*)(bufB + (size_t)(i2*TPB + t)*16) = r[i2];
        }
        __syncthreads();

        #pragma unroll
        for (int tile = 0; tile < 8; ++tile){
            const int jl = w*64 + tile*8 + (lane>>2);   // local B row
            const char* baddr = bufB + (size_t)jl*STRB + (lane&3)*4;
            float d0=0.f, d1=0.f, d2=0.f, d3=0.f;
            #pragma unroll
            for (int ks = 0; ks < 3; ++ks){
                uint32_t b0 = *(const uint32_t*)(baddr + ks*32);
                uint32_t b1 = *(const uint32_t*)(baddr + ks*32 + 16);
                asm volatile("mma.sync.aligned.m16n8k16.row.col.f32.bf16.bf16.f32 "
                    "{%0,%1,%2,%3}, {%4,%5,%6,%7}, {%8,%9}, {%0,%1,%2,%3};"
                    : "+f"(d0), "+f"(d1), "+f"(d2), "+f"(d3)
                    : "r"(afr[ks][0]), "r"(afr[ks][1]), "r"(afr[ks][2]), "r"(afr[ks][3]),
                      "r"(b0), "r"(b1));
            }
            const int jcol = s*1024 + w*64 + tile*8 + 2*(lane&3);
            uint32_t pk0, pk1;
            asm("cvt.rn.satfinite.bf16x2.f32 %0, %1, %2;" : "=r"(pk0) : "f"(d1), "f"(d0));
            asm("cvt.rn.satfinite.bf16x2.f32 %0, %1, %2;" : "=r"(pk1) : "f"(d3), "f"(d2));
            const int sw = jcol >> 1;
            sS[r0*SSTR + sw] = pk0;
            sS[r1*SSTR + sw] = pk1;
            kmin0 = min(kmin0, min(((pk0 & 0xffffu) << 11) | (uint32_t)jcol,
                                   ((pk0 >> 16)     << 11) | (uint32_t)(jcol+1)));
            kmin1 = min(kmin1, min(((pk1 & 0xffffu) << 11) | (uint32_t)jcol,
                                   ((pk1 >> 16)     << 11) | (uint32_t)(jcol+1)));
        }
        __syncthreads();
    }

    // publish per-(row, warp, lane&3) mins: 64 keys per row
    probeK[r0*68 + w*4 + (lane&3)] = kmin0;
    probeK[r1*68 + w*4 + (lane&3)] = kmin1;
    __syncthreads();

    // ---- probe: warp w handles row w; 16 distinct probes -> threshold ----
    const int n = i0 + w;
    const float* qrow = q + ((size_t)b*NN + n)*NN;
    uint32_t ub;
    {
        uint32_t ka = probeK[w*68 + lane];
        uint32_t kb = probeK[w*68 + 32 + lane];
        uint32_t k = min(ka, kb);
        uint32_t k2 = min(k, __shfl_xor_sync(0xffffffffu, k, 1));
        uint32_t kp = __shfl_sync(0xffffffffu, k2, (lane & 15)*2);
        int jp = (int)(kp & 2047u);
        float Dq = __uint_as_float((kp >> 11) << 16) - 16.f;
        float sp = ET * fmaxf(Dq, 0.f);
        float T = sp - logf(-logf(__ldg(qrow + jp) + EPSF));
        #pragma unroll
        for (int o = 16; o; o >>= 1) T = fmaxf(T, __shfl_xor_sync(0xffffffffu, T, o));
        float tauf = (T + NM)/ET + 2.f*ERRD + 1.2f + 16.f;
        ub = (__float_as_uint(tauf) + 0xffffu) >> 16;
    }

    // ---- scan + chunked exact merge (deterministic, no atomics) ----
    const uint32_t* srow = sS + w*SSTR;
    int* stg = stgAll + w*48;
    const ull* wi = (const ull*)(hiF + w*FOUT);
    const float sqv = sqiS[w];
    const unsigned lm = (1u << lane) - 1u;
    float bv = finf(); int bj = 0x7fffffff;
    int cnt = 0;
    for (int m = 0; m < 32; ++m){
        uint32_t wv = srow[lane + 32*m];
        int jb2 = 2*(lane + 32*m);
        bool c0 = (wv & 0xffffu) <= ub;
        bool c1 = (wv >> 16)     <= ub;
        unsigned m0 = __ballot_sync(0xffffffffu, c0);
        unsigned m1 = __ballot_sync(0xffffffffu, c1);
        if (m0 | m1){
            int n0c = __popc(m0);
            if (c0) stg[cnt + __popc(m0 & lm)] = jb2;
            if (c1) stg[cnt + n0c + __popc(m1 & lm)] = jb2 + 1;
            cnt += n0c + __popc(m1);
            __syncwarp();
            while (cnt >= 16){
                float v = bv; int jj = bj;
                if (lane >= 16){
                    int j2 = stg[cnt - 16 + (lane - 16)];
                    const ull* aj = (const ull*)(hb + (size_t)j2*FOUT);
                    ull acc = 0ull;
                    #pragma unroll
                    for (int dp = 0; dp < 16; ++dp) acc = ffma2(aj[dp], wi[dp], acc);
                    float2 f = unpackf2(acc);
                    float s2 = ET * fmaxf(sqv + g_sq[b*NN + j2] - 2.f*(f.x + f.y), 0.f);
                    v = s2 - logf(-logf(__ldg(qrow + j2) + EPSF)); jj = j2;
                }
                bsort32(lane, v, jj);
                bv = v; bj = jj;
                cnt -= 16;
            }
        }
    }
    if (cnt > 0){
        float v = bv; int jj = bj;
        if (lane >= 16){
            int idx = lane - 16;
            if (idx < cnt){
                int j2 = stg[idx];
                const ull* aj = (const ull*)(hb + (size_t)j2*FOUT);
                ull acc = 0ull;
                #pragma unroll
                for (int dp = 0; dp < 16; ++dp) acc = ffma2(aj[dp], wi[dp], acc);
                float2 f = unpackf2(acc);
                float s2 = ET * fmaxf(sqv + g_sq[b*NN + j2] - 2.f*(f.x + f.y), 0.f);
                v = s2 - logf(-logf(__ldg(qrow + j2) + EPSF)); jj = j2;
            } else { v = finf(); jj = 0x7fffffff; }
        }
        bsort32(lane, v, jj);
        bv = v; bj = jj;
    }

    // ---- emit ----
    if (lane < KK){
        size_t base = ((size_t)b*NN + n)*KK + lane;
        lp[base] = -bv;
        e0[base] = (float)(bj + b*NN);
        e0[base + BNK] = (float)(n + b*NN);
    }
}

extern "C" void kernel_launch(void* const* d_in, const int* in_sizes, int n_in,
                              void* d_out, int out_size){
    const float* x    = (const float*)d_in[0];
    const float* W    = (const float*)d_in[1];
    const float* temp = (const float*)d_in[2];
    const float* q    = (const float*)d_in[3];
    float* out  = (float*)d_out;
    float* hout = out;                   // [B,N,Fout]
    float* e0   = out + H_ELEMS;         // [2, B*N*K]
    float* lp   = out + H_ELEMS + 2*BNK; // [B,N,K]

    k_embed<<<BB*NN/8, 256>>>(x, W, hout);

    cudaFuncSetAttribute(k_main, cudaFuncAttributeMaxDynamicSharedMemorySize, SMEM_DYN);
    k_main<<<BB*(NN/MT), TPB, SMEM_DYN>>>(hout, q, temp, e0, lp);
}

// round 14
// speedup vs baseline: 1.5271x; 1.1935x over previous
#include <cuda_runtime.h>
#include <cuda_bf16.h>
#include <cstdint>

#define BB   16
#define NN   2048
#define FINN 64
#define FOUT 32
#define KK   16
#define MT   16              /* i-rows per block */
#define TPB  512
#define STR  48              /* bf16 per augmented row (k=48) */
#define STRB 96              /* bytes per augmented row */
#define SSTR 1036            /* padded words per score-cache row */
#define EPSF 1e-8f
#define NM   2.9150f         /* -log(-log(eps)) = 2.91347 */
#define ERRD 1.0f
#define H_ELEMS (BB*NN*FOUT)
#define BNK     (BB*NN*KK)

__device__ float g_sq[BB*NN];
__device__ __nv_bfloat16 g_A[(size_t)BB*NN*STR];
__device__ __nv_bfloat16 g_B[(size_t)BB*NN*STR];

typedef unsigned long long ull;

static __device__ __forceinline__ ull ffma2(ull a, ull b, ull c){
    ull d; asm("fma.rn.f32x2 %0, %1, %2, %3;" : "=l"(d) : "l"(a), "l"(b), "l"(c));
    return d;
}
static __device__ __forceinline__ float2 unpackf2(ull v){
    float2 f; uint32_t lo, hi;
    asm("mov.b64 {%0, %1}, %2;" : "=r"(lo), "=r"(hi) : "l"(v));
    f.x = __uint_as_float(lo); f.y = __uint_as_float(hi);
    return f;
}
static __device__ __forceinline__ float finf(){ return __int_as_float(0x7f800000); }
static __device__ __forceinline__ bool lessvi(float v1, int j1, float v2, int j2){
    return (v1 < v2) || (v1 == v2 && j1 < j2);
}
static __device__ __forceinline__ void bsort32(int lane, float& v, int& j){
    #pragma unroll
    for (int k = 2; k <= 32; k <<= 1){
        #pragma unroll
        for (int s = k >> 1; s > 0; s >>= 1){
            float ov = __shfl_xor_sync(0xffffffffu, v, s);
            int   oj = __shfl_xor_sync(0xffffffffu, j, s);
            bool takeMin = (((lane & k) == 0) == ((lane & s) == 0));
            bool oless   = lessvi(ov, oj, v, j);
            if (takeMin ? oless : !oless){ v = ov; j = oj; }
        }
    }
}

// ---------------- kernel 1: h = x@W, sq, augmented bf16 rows ----------------
__global__ void k_embed(const float* __restrict__ x, const float* __restrict__ W,
                        float* __restrict__ hout){
    __shared__ float Ws[FINN*FOUT];
    __shared__ float xs[8][FINN];
    int t = threadIdx.x;
    for (int i = t; i < FINN*FOUT; i += 256) Ws[i] = W[i];
    int row0 = blockIdx.x * 8;
    for (int i = t; i < 8*FINN; i += 256){
        int r = i / FINN, f = i % FINN;
        xs[r][f] = x[(size_t)(row0 + r)*FINN + f];
    }
    __syncthreads();
    int r = t >> 5, d = t & 31;
    float acc = 0.f;
    #pragma unroll
    for (int f = 0; f < FINN; ++f)
        acc = fmaf(xs[r][f], Ws[f*FOUT + d], acc);
    int row = row0 + r;
    hout[(size_t)row*FOUT + d] = acc;
    __nv_bfloat16 hbf = __float2bfloat16(acc);
    g_A[(size_t)row*STR + d] = hbf;
    g_B[(size_t)row*STR + d] = __float2bfloat16(-2.f*__bfloat162float(hbf));
    float v = acc * acc;
    #pragma unroll
    for (int o = 16; o; o >>= 1) v += __shfl_xor_sync(0xffffffffu, v, o);
    if (d == 0) g_sq[row] = v;
    // aug cols 32..47: A=[sq,1,4,0..], B=[1,sq,4,0..] -> D~ = -2h.h + sqi + sqj + 16
    if (d < 16){
        float av = 0.f, bv = 0.f;
        if (d == 0){ av = v;   bv = 1.f; }
        else if (d == 1){ av = 1.f; bv = v; }
        else if (d == 2){ av = 4.f; bv = 4.f; }
        g_A[(size_t)row*STR + 32 + d] = __float2bfloat16(av);
        g_B[(size_t)row*STR + 32 + d] = __float2bfloat16(bv);
    }
}

// dyn smem layout (bytes)
#define O_SS   0u                 /* 16 * SSTR * 4 score cache = 66304 */
#define O_HI   66304u             /* 16*32 f32 exact h rows    = 2048  */
#define O_PK   68352u             /* 16*68 keys (padded)       = 4352  */
#define O_STG  72704u             /* 16*48 candidate stage     = 3072  */
#define O_SQI  75776u             /* 16 f32                    = 64    */
#define SMEM_DYN 75840u

// ---------------- kernel 2: HMMA gram (direct-LDG B) + exact gumbel top-k ----------------
__global__ __launch_bounds__(TPB, 2)
void k_main(const float* __restrict__ h, const float* __restrict__ q,
            const float* __restrict__ temp,
            float* __restrict__ e0, float* __restrict__ lp){
    extern __shared__ char sm[];
    uint32_t* sS    = (uint32_t*)(sm + O_SS);
    float*    hiF   = (float*)(sm + O_HI);
    uint32_t* probeK= (uint32_t*)(sm + O_PK);
    int*      stgAll= (int*)(sm + O_STG);
    float*    sqiS  = (float*)(sm + O_SQI);

    const int t = threadIdx.x, w = t >> 5, lane = t & 31;
    const int b  = blockIdx.x >> 7;
    const int i0 = (blockIdx.x & 127) * MT;
    const float* hb = h + (size_t)b*NN*FOUT;
    const char* gBp = (const char*)(g_B + (size_t)b*NN*STR);
    const float ET = expf(fminf(fmaxf(temp[0], -5.f), 5.f));

    for (int g = t; g < MT*FOUT/4; g += TPB)
        ((float4*)hiF)[g] = ((const float4*)(hb + (size_t)i0*FOUT))[g];
    if (t < MT) sqiS[t] = g_sq[b*NN + i0 + t];

    // A fragments: 3 k-steps of m16n8k16, rows i0+(lane>>2), +8 (validated mapping)
    uint32_t afr[3][4];
    {
        const char* pr0 = (const char*)(g_A + (size_t)(b*NN + i0 + (lane>>2))*STR);
        const char* pr1 = pr0 + 8*STRB;
        #pragma unroll
        for (int ks = 0; ks < 3; ++ks){
            int byt = ks*32 + (lane&3)*4;
            afr[ks][0] = *(const uint32_t*)(pr0 + byt);
            afr[ks][1] = *(const uint32_t*)(pr1 + byt);
            afr[ks][2] = *(const uint32_t*)(pr0 + byt + 16);
            afr[ks][3] = *(const uint32_t*)(pr1 + byt + 16);
        }
    }

    uint32_t kmin0 = 0xffffffffu, kmin1 = 0xffffffffu;
    const int r0 = lane >> 2, r1 = (lane >> 2) + 8;

    // ---- gram: warp w covers j in [w*128, w*128+128), 16 tiles of 8 rows ----
    // B fragments loaded straight from global (L2-resident), pipelined 1 tile ahead.
    const char* bbase = gBp + (size_t)(w*128 + (lane>>2))*STRB + (lane&3)*4;
    uint32_t pb[6];
    #pragma unroll
    for (int ks = 0; ks < 3; ++ks){
        pb[2*ks]   = *(const uint32_t*)(bbase + ks*32);
        pb[2*ks+1] = *(const uint32_t*)(bbase + ks*32 + 16);
    }
    #pragma unroll
    for (int tile = 0; tile < 16; ++tile){
        uint32_t cb[6];
        #pragma unroll
        for (int u = 0; u < 6; ++u) cb[u] = pb[u];
        if (tile < 15){
            const char* nb = bbase + (size_t)(tile+1)*8*STRB;
            #pragma unroll
            for (int ks = 0; ks < 3; ++ks){
                pb[2*ks]   = *(const uint32_t*)(nb + ks*32);
                pb[2*ks+1] = *(const uint32_t*)(nb + ks*32 + 16);
            }
        }
        float d0=0.f, d1=0.f, d2=0.f, d3=0.f;
        #pragma unroll
        for (int ks = 0; ks < 3; ++ks){
            asm volatile("mma.sync.aligned.m16n8k16.row.col.f32.bf16.bf16.f32 "
                "{%0,%1,%2,%3}, {%4,%5,%6,%7}, {%8,%9}, {%0,%1,%2,%3};"
                : "+f"(d0), "+f"(d1), "+f"(d2), "+f"(d3)
                : "r"(afr[ks][0]), "r"(afr[ks][1]), "r"(afr[ks][2]), "r"(afr[ks][3]),
                  "r"(cb[2*ks]), "r"(cb[2*ks+1]));
        }
        const int jcol = w*128 + tile*8 + 2*(lane&3);
        uint32_t pk0, pk1;
        asm("cvt.rn.satfinite.bf16x2.f32 %0, %1, %2;" : "=r"(pk0) : "f"(d1), "f"(d0));
        asm("cvt.rn.satfinite.bf16x2.f32 %0, %1, %2;" : "=r"(pk1) : "f"(d3), "f"(d2));
        const int sw = jcol >> 1;
        sS[r0*SSTR + sw] = pk0;
        sS[r1*SSTR + sw] = pk1;
        kmin0 = min(kmin0, min(((pk0 & 0xffffu) << 11) | (uint32_t)jcol,
                               ((pk0 >> 16)     << 11) | (uint32_t)(jcol+1)));
        kmin1 = min(kmin1, min(((pk1 & 0xffffu) << 11) | (uint32_t)jcol,
                               ((pk1 >> 16)     << 11) | (uint32_t)(jcol+1)));
    }

    // publish per-(row, warp, lane&3) mins: 64 keys per row
    probeK[r0*68 + w*4 + (lane&3)] = kmin0;
    probeK[r1*68 + w*4 + (lane&3)] = kmin1;
    __syncthreads();

    // ---- probe: warp w handles row w; 16 distinct probes -> threshold ----
    const int n = i0 + w;
    const float* qrow = q + ((size_t)b*NN + n)*NN;
    uint32_t ub;
    {
        uint32_t ka = probeK[w*68 + lane];
        uint32_t kb = probeK[w*68 + 32 + lane];
        uint32_t k = min(ka, kb);
        uint32_t k2 = min(k, __shfl_xor_sync(0xffffffffu, k, 1));
        uint32_t kp = __shfl_sync(0xffffffffu, k2, (lane & 15)*2);
        int jp = (int)(kp & 2047u);
        float Dq = __uint_as_float((kp >> 11) << 16) - 16.f;
        float sp = ET * fmaxf(Dq, 0.f);
        float T = sp - logf(-logf(__ldg(qrow + jp) + EPSF));
        #pragma unroll
        for (int o = 16; o; o >>= 1) T = fmaxf(T, __shfl_xor_sync(0xffffffffu, T, o));
        float tauf = (T + NM)/ET + 2.f*ERRD + 1.2f + 16.f;
        ub = (__float_as_uint(tauf) + 0xffffu) >> 16;
    }

    // ---- scan + chunked exact merge (deterministic, no atomics) ----
    const uint32_t* srow = sS + w*SSTR;
    int* stg = stgAll + w*48;
    const ull* wi = (const ull*)(hiF + w*FOUT);
    const float sqv = sqiS[w];
    const unsigned lm = (1u << lane) - 1u;
    float bv = finf(); int bj = 0x7fffffff;
    int cnt = 0;
    for (int m = 0; m < 32; ++m){
        uint32_t wv = srow[lane + 32*m];
        int jb2 = 2*(lane + 32*m);
        bool c0 = (wv & 0xffffu) <= ub;
        bool c1 = (wv >> 16)     <= ub;
        unsigned m0 = __ballot_sync(0xffffffffu, c0);
        unsigned m1 = __ballot_sync(0xffffffffu, c1);
        if (m0 | m1){
            int n0c = __popc(m0);
            if (c0) stg[cnt + __popc(m0 & lm)] = jb2;
            if (c1) stg[cnt + n0c + __popc(m1 & lm)] = jb2 + 1;
            cnt += n0c + __popc(m1);
            __syncwarp();
            while (cnt >= 16){
                float v = bv; int jj = bj;
                if (lane >= 16){
                    int j2 = stg[cnt - 16 + (lane - 16)];
                    const ull* aj = (const ull*)(hb + (size_t)j2*FOUT);
                    ull acc = 0ull;
                    #pragma unroll
                    for (int dp = 0; dp < 16; ++dp) acc = ffma2(aj[dp], wi[dp], acc);
                    float2 f = unpackf2(acc);
                    float s2 = ET * fmaxf(sqv + g_sq[b*NN + j2] - 2.f*(f.x + f.y), 0.f);
                    v = s2 - logf(-logf(__ldg(qrow + j2) + EPSF)); jj = j2;
                }
                bsort32(lane, v, jj);
                bv = v; bj = jj;
                cnt -= 16;
            }
        }
    }
    if (cnt > 0){
        float v = bv; int jj = bj;
        if (lane >= 16){
            int idx = lane - 16;
            if (idx < cnt){
                int j2 = stg[idx];
                const ull* aj = (const ull*)(hb + (size_t)j2*FOUT);
                ull acc = 0ull;
                #pragma unroll
                for (int dp = 0; dp < 16; ++dp) acc = ffma2(aj[dp], wi[dp], acc);
                float2 f = unpackf2(acc);
                float s2 = ET * fmaxf(sqv + g_sq[b*NN + j2] - 2.f*(f.x + f.y), 0.f);
                v = s2 - logf(-logf(__ldg(qrow + j2) + EPSF)); jj = j2;
            } else { v = finf(); jj = 0x7fffffff; }
        }
        bsort32(lane, v, jj);
        bv = v; bj = jj;
    }

    // ---- emit ----
    if (lane < KK){
        size_t base = ((size_t)b*NN + n)*KK + lane;
        lp[base] = -bv;
        e0[base] = (float)(bj + b*NN);
        e0[base + BNK] = (float)(n + b*NN);
    }
}

extern "C" void kernel_launch(void* const* d_in, const int* in_sizes, int n_in,
                              void* d_out, int out_size){
    const float* x    = (const float*)d_in[0];
    const float* W    = (const float*)d_in[1];
    const float* temp = (const float*)d_in[2];
    const float* q    = (const float*)d_in[3];
    float* out  = (float*)d_out;
    float* hout = out;                   // [B,N,Fout]
    float* e0   = out + H_ELEMS;         // [2, B*N*K]
    float* lp   = out + H_ELEMS + 2*BNK; // [B,N,K]

    k_embed<<<BB*NN/8, 256>>>(x, W, hout);

    cudaFuncSetAttribute(k_main, cudaFuncAttributeMaxDynamicSharedMemorySize, SMEM_DYN);
    k_main<<<BB*(NN/MT), TPB, SMEM_DYN>>>(hout, q, temp, e0, lp);
}

// round 17
// speedup vs baseline: 2.1794x; 1.4272x over previous
#include <cuda_runtime.h>
#include <cuda_bf16.h>
#include <cstdint>

#define BB   16
#define NN   2048
#define FINN 64
#define FOUT 32
#define KK   16
#define MT   16              /* i-rows per block */
#define TPB  512
#define STR  48              /* bf16 per augmented A row (k=48) */
#define STRB 96              /* bytes per augmented A row */
#define SSTR 1036            /* padded words per score-cache row */
#define EPSF 1e-8f
#define NM   2.9150f         /* -log(-log(eps)) = 2.91347 */
#define ERRD 1.0f
#define H_ELEMS (BB*NN*FOUT)
#define BNK     (BB*NN*KK)

__device__ float g_sq[BB*NN];
__device__ __nv_bfloat16 g_A[(size_t)BB*NN*STR];
__device__ uint32_t g_Bf[(size_t)BB*(NN/8)*6*32];   /* B in MMA fragment order */

typedef unsigned long long ull;

static __device__ __forceinline__ ull ffma2(ull a, ull b, ull c){
    ull d; asm("fma.rn.f32x2 %0, %1, %2, %3;" : "=l"(d) : "l"(a), "l"(b), "l"(c));
    return d;
}
static __device__ __forceinline__ float2 unpackf2(ull v){
    float2 f; uint32_t lo, hi;
    asm("mov.b64 {%0, %1}, %2;" : "=r"(lo), "=r"(hi) : "l"(v));
    f.x = __uint_as_float(lo); f.y = __uint_as_float(hi);
    return f;
}
static __device__ __forceinline__ float finf(){ return __int_as_float(0x7f800000); }
static __device__ __forceinline__ bool lessvi(float v1, int j1, float v2, int j2){
    return (v1 < v2) || (v1 == v2 && j1 < j2);
}
static __device__ __forceinline__ void bsort32(int lane, float& v, int& j){
    #pragma unroll
    for (int k = 2; k <= 32; k <<= 1){
        #pragma unroll
        for (int s = k >> 1; s > 0; s >>= 1){
            float ov = __shfl_xor_sync(0xffffffffu, v, s);
            int   oj = __shfl_xor_sync(0xffffffffu, j, s);
            bool takeMin = (((lane & k) == 0) == ((lane & s) == 0));
            bool oless   = lessvi(ov, oj, v, j);
            if (takeMin ? oless : !oless){ v = ov; j = oj; }
        }
    }
}

// ---------------- kernel 1: h = x@W, sq, A rows + fragment-order B ----------------
__global__ void k_embed(const float* __restrict__ x, const float* __restrict__ W,
                        float* __restrict__ hout){
    __shared__ float Ws[FINN*FOUT];
    __shared__ float xs[8][FINN];
    __shared__ float hr[8][33];          /* per-warp -2h row buffer (UB-free packing) */
    int t = threadIdx.x;
    for (int i = t; i < FINN*FOUT; i += 256) Ws[i] = W[i];
    int row0 = blockIdx.x * 8;
    for (int i = t; i < 8*FINN; i += 256){
        int r = i / FINN, f = i % FINN;
        xs[r][f] = x[(size_t)(row0 + r)*FINN + f];
    }
    __syncthreads();
    int r = t >> 5, d = t & 31;
    float acc = 0.f;
    #pragma unroll
    for (int f = 0; f < FINN; ++f)
        acc = fmaf(xs[r][f], Ws[f*FOUT + d], acc);
    int row = row0 + r;
    hout[(size_t)row*FOUT + d] = acc;
    __nv_bfloat16 hbf = __float2bfloat16(acc);
    g_A[(size_t)row*STR + d] = hbf;
    float v = acc * acc;
    #pragma unroll
    for (int o = 16; o; o >>= 1) v += __shfl_xor_sync(0xffffffffu, v, o);
    if (d == 0) g_sq[row] = v;
    // A aug cols 32..47 = [sq, 1, 4, 0...]
    if (d < 16){
        float av = (d == 0) ? v : ((d == 1) ? 1.f : ((d == 2) ? 4.f : 0.f));
        g_A[(size_t)row*STR + 32 + d] = __float2bfloat16(av);
    }
    // B in fragment order: row vector = [-2h (32), 1, sq, 4, 0...], word p packs cols (2p, 2p+1)
    hr[r][d] = -2.f*__bfloat162float(hbf);
    __syncwarp();
    {
        float lo, hi;
        if (d < 16){ lo = hr[r][2*d]; hi = hr[r][2*d + 1]; }
        else if (d == 16){ lo = 1.f; hi = v; }       // cols 32,33 = (1, sq)
        else if (d == 17){ lo = 4.f; hi = 0.f; }      // cols 34,35 = (4, 0)
        else { lo = 0.f; hi = 0.f; }
        if (d < 24){
            uint32_t pk;
            asm("cvt.rn.bf16x2.f32 %0, %1, %2;" : "=r"(pk) : "f"(hi), "f"(lo));
            int f = (d < 16) ? ((d >> 3)*2 + ((d >> 2) & 1)) : (4 + ((d >> 2) & 1));
            g_Bf[(((size_t)row >> 3)*6 + f)*32 + (row & 7)*4 + (d & 3)] = pk;
        }
    }
}

// dyn smem layout (bytes)
#define O_SS   0u                 /* 16 * SSTR * 4 score cache = 66304 */
#define O_HI   66304u             /* 16*32 f32 exact h rows    = 2048  */
#define O_PK   68352u             /* 16*68 keys (padded)       = 4352  */
#define O_STG  72704u             /* 16*80 candidate stage     = 5120  */
#define O_SQI  77824u             /* 16 f32                    = 64    */
#define SMEM_DYN 77888u

// ---------------- kernel 2: HMMA gram (coalesced frag B) + exact gumbel top-k ----------------
__global__ __launch_bounds__(TPB, 2)
void k_main(const float* __restrict__ h, const float* __restrict__ q,
            const float* __restrict__ temp,
            float* __restrict__ e0, float* __restrict__ lp){
    extern __shared__ char sm[];
    uint32_t* sS    = (uint32_t*)(sm + O_SS);
    float*    hiF   = (float*)(sm + O_HI);
    uint32_t* probeK= (uint32_t*)(sm + O_PK);
    int*      stgAll= (int*)(sm + O_STG);
    float*    sqiS  = (float*)(sm + O_SQI);

    const int t = threadIdx.x, w = t >> 5, lane = t & 31;
    const int b  = blockIdx.x >> 7;
    const int i0 = (blockIdx.x & 127) * MT;
    const float* hb = h + (size_t)b*NN*FOUT;
    const float ET = expf(fminf(fmaxf(temp[0], -5.f), 5.f));

    for (int g = t; g < MT*FOUT/4; g += TPB)
        ((float4*)hiF)[g] = ((const float4*)(hb + (size_t)i0*FOUT))[g];
    if (t < MT) sqiS[t] = g_sq[b*NN + i0 + t];

    // A fragments: 3 k-steps of m16n8k16, rows i0+(lane>>2), +8 (validated mapping)
    uint32_t afr[3][4];
    {
        const char* pr0 = (const char*)(g_A + (size_t)(b*NN + i0 + (lane>>2))*STR);
        const char* pr1 = pr0 + 8*STRB;
        #pragma unroll
        for (int ks = 0; ks < 3; ++ks){
            int byt = ks*32 + (lane&3)*4;
            afr[ks][0] = *(const uint32_t*)(pr0 + byt);
            afr[ks][1] = *(const uint32_t*)(pr1 + byt);
            afr[ks][2] = *(const uint32_t*)(pr0 + byt + 16);
            afr[ks][3] = *(const uint32_t*)(pr1 + byt + 16);
        }
    }

    uint32_t kmin0 = 0xffffffffu, kmin1 = 0xffffffffu;
    const int r0 = lane >> 2, r1 = (lane >> 2) + 8;

    // ---- gram: warp w covers j in [w*128, w*128+128) = 16 groups of 8 rows ----
    // B fragments in coalesced fragment order: 6 words x 32 lanes per group (nL=1 loads).
    const uint32_t* bfp = g_Bf + ((size_t)b*(NN/8) + w*16)*6*32 + lane;
    uint32_t pb[6];
    #pragma unroll
    for (int u = 0; u < 6; ++u) pb[u] = bfp[u*32];
    #pragma unroll
    for (int tile = 0; tile < 16; ++tile){
        uint32_t cb[6];
        #pragma unroll
        for (int u = 0; u < 6; ++u) cb[u] = pb[u];
        if (tile < 15){
            const uint32_t* nb = bfp + (size_t)(tile+1)*192;
            #pragma unroll
            for (int u = 0; u < 6; ++u) pb[u] = nb[u*32];
        }
        float d0=0.f, d1=0.f, d2=0.f, d3=0.f;
        #pragma unroll
        for (int ks = 0; ks < 3; ++ks){
            asm volatile("mma.sync.aligned.m16n8k16.row.col.f32.bf16.bf16.f32 "
                "{%0,%1,%2,%3}, {%4,%5,%6,%7}, {%8,%9}, {%0,%1,%2,%3};"
                : "+f"(d0), "+f"(d1), "+f"(d2), "+f"(d3)
                : "r"(afr[ks][0]), "r"(afr[ks][1]), "r"(afr[ks][2]), "r"(afr[ks][3]),
                  "r"(cb[2*ks]), "r"(cb[2*ks+1]));
        }
        const int jcol = w*128 + tile*8 + 2*(lane&3);
        uint32_t pk0, pk1;
        asm("cvt.rn.satfinite.bf16x2.f32 %0, %1, %2;" : "=r"(pk0) : "f"(d1), "f"(d0));
        asm("cvt.rn.satfinite.bf16x2.f32 %0, %1, %2;" : "=r"(pk1) : "f"(d3), "f"(d2));
        const int sw = jcol >> 1;
        sS[r0*SSTR + sw] = pk0;
        sS[r1*SSTR + sw] = pk1;
        kmin0 = min(kmin0, min(((pk0 & 0xffffu) << 11) | (uint32_t)jcol,
                               ((pk0 >> 16)     << 11) | (uint32_t)(jcol+1)));
        kmin1 = min(kmin1, min(((pk1 & 0xffffu) << 11) | (uint32_t)jcol,
                               ((pk1 >> 16)     << 11) | (uint32_t)(jcol+1)));
    }

    // publish per-(row, warp, lane&3) mins: 64 keys per row
    probeK[r0*68 + w*4 + (lane&3)] = kmin0;
    probeK[r1*68 + w*4 + (lane&3)] = kmin1;
    __syncthreads();

    // ---- probe: warp w handles row w; 16 distinct probes -> threshold ----
    const int n = i0 + w;
    const float* qrow = q + ((size_t)b*NN + n)*NN;
    uint32_t ub;
    {
        uint32_t ka = probeK[w*68 + lane];
        uint32_t kb = probeK[w*68 + 32 + lane];
        uint32_t k = min(ka, kb);
        uint32_t k2 = min(k, __shfl_xor_sync(0xffffffffu, k, 1));
        uint32_t kp = __shfl_sync(0xffffffffu, k2, (lane & 15)*2);
        int jp = (int)(kp & 2047u);
        float Dq = __uint_as_float((kp >> 11) << 16) - 16.f;
        float sp = ET * fmaxf(Dq, 0.f);
        float T = sp - logf(-logf(__ldg(qrow + jp) + EPSF));
        #pragma unroll
        for (int o = 16; o; o >>= 1) T = fmaxf(T, __shfl_xor_sync(0xffffffffu, T, o));
        float tauf = (T + NM)/ET + 2.f*ERRD + 1.2f + 16.f;
        ub = (__float_as_uint(tauf) + 0xffffu) >> 16;
    }

    // ---- scan + chunked exact merge (deterministic, no atomics) ----
    const uint32_t* srow = sS + w*SSTR;
    int* stg = stgAll + w*80;
    const ull* wi = (const ull*)(hiF + w*FOUT);
    const float sqv = sqiS[w];
    const unsigned lm = (1u << lane) - 1u;
    float bv = finf(); int bj = 0x7fffffff;
    int cnt = 0;
    for (int m = 0; m < 32; ++m){
        uint32_t wv = srow[lane + 32*m];
        int jb2 = 2*(lane + 32*m);
        bool c0 = (wv & 0xffffu) <= ub;
        bool c1 = (wv >> 16)     <= ub;
        unsigned m0 = __ballot_sync(0xffffffffu, c0);
        unsigned m1 = __ballot_sync(0xffffffffu, c1);
        if (m0 | m1){
            int n0c = __popc(m0);
            if (c0) stg[cnt + __popc(m0 & lm)] = jb2;
            if (c1) stg[cnt + n0c + __popc(m1 & lm)] = jb2 + 1;
            cnt += n0c + __popc(m1);
            __syncwarp();
            while (cnt >= 16){
                float v = bv; int jj = bj;
                if (lane >= 16){
                    int j2 = stg[cnt - 16 + (lane - 16)];
                    const ulonglong2* aj = (const ulonglong2*)(hb + (size_t)j2*FOUT);
                    ull acc = 0ull;
                    #pragma unroll
                    for (int dp = 0; dp < 8; ++dp){
                        ulonglong2 u = aj[dp];
                        acc = ffma2(u.x, wi[2*dp], acc);
                        acc = ffma2(u.y, wi[2*dp+1], acc);
                    }
                    float2 f = unpackf2(acc);
                    float s2 = ET * fmaxf(sqv + g_sq[b*NN + j2] - 2.f*(f.x + f.y), 0.f);
                    v = s2 - logf(-logf(__ldg(qrow + j2) + EPSF)); jj = j2;
                }
                bsort32(lane, v, jj);
                bv = v; bj = jj;
                cnt -= 16;
            }
        }
    }
    if (cnt > 0){
        float v = bv; int jj = bj;
        if (lane >= 16){
            int idx = lane - 16;
            if (idx < cnt){
                int j2 = stg[idx];
                const ulonglong2* aj = (const ulonglong2*)(hb + (size_t)j2*FOUT);
                ull acc = 0ull;
                #pragma unroll
                for (int dp = 0; dp < 8; ++dp){
                    ulonglong2 u = aj[dp];
                    acc = ffma2(u.x, wi[2*dp], acc);
                    acc = ffma2(u.y, wi[2*dp+1], acc);
                }
                float2 f = unpackf2(acc);
                float s2 = ET * fmaxf(sqv + g_sq[b*NN + j2] - 2.f*(f.x + f.y), 0.f);
                v = s2 - logf(-logf(__ldg(qrow + j2) + EPSF)); jj = j2;
            } else { v = finf(); jj = 0x7fffffff; }
        }
        bsort32(lane, v, jj);
        bv = v; bj = jj;
    }

    // ---- emit ----
    if (lane < KK){
        size_t base = ((size_t)b*NN + n)*KK + lane;
        lp[base] = -bv;
        e0[base] = (float)(bj + b*NN);
        e0[base + BNK] = (float)(n + b*NN);
    }
}

extern "C" void kernel_launch(void* const* d_in, const int* in_sizes, int n_in,
                              void* d_out, int out_size){
    const float* x    = (const float*)d_in[0];
    const float* W    = (const float*)d_in[1];
    const float* temp = (const float*)d_in[2];
    const float* q    = (const float*)d_in[3];
    float* out  = (float*)d_out;
    float* hout = out;                   // [B,N,Fout]
    float* e0   = out + H_ELEMS;         // [2, B*N*K]
    float* lp   = out + H_ELEMS + 2*BNK; // [B,N,K]

    k_embed<<<BB*NN/8, 256>>>(x, W, hout);

    cudaFuncSetAttribute(k_main, cudaFuncAttributeMaxDynamicSharedMemorySize, SMEM_DYN);
    k_main<<<BB*(NN/MT), TPB, SMEM_DYN>>>(hout, q, temp, e0, lp);
}